// round 9
// baseline (speedup 1.0000x reference)
#include <cuda_runtime.h>
#include <cuda_fp16.h>
#include <math.h>
#include <stdint.h>

#define T_TOKENS 8192
#define HDIM 1024
#define IDIM 512
#define NEXP 32
#define TOPK 4
#define TILE_M 128
#define KC 64
#define STAGE 36864            // bytes per pipeline stage
#define NSTAGE 3
#define WG_OFF 18432           // Phase A: A[128x144B], Wg[64x144B], Wu[64x144B]
#define WU_OFF 27648
#define WD_OFF 18432           // Phase B: A[128x144B], Wd[64x272B]

// ---------------- device scratch ----------------
__device__ float  g_partial[(size_t)T_TOKENS * TOPK * HDIM];   // 128 MB fp32
__device__ __half g_hh[(size_t)T_TOKENS * TOPK * IDIM];        // 32 MB
__device__ __half g_xh[(size_t)T_TOKENS * HDIM];               // 16 MB
__device__ __half g_wgh[(size_t)NEXP * HDIM * IDIM];           // 32 MB [E][H][I] (k-major)
__device__ __half g_wuh[(size_t)NEXP * HDIM * IDIM];           // 32 MB [E][H][I]
__device__ __half g_wdh[(size_t)NEXP * IDIM * HDIM];           // 32 MB [E][I][H] (k-major)
__device__ int    g_top_idx[T_TOKENS * TOPK];
__device__ float  g_top_wt [T_TOKENS * TOPK];
__device__ int    g_cnt[NEXP];
__device__ int    g_off[NEXP];
__device__ int    g_etok[NEXP * T_TOKENS];
__device__ float  g_ewt [NEXP * T_TOKENS];
__device__ int    g_tiles[2048];
__device__ int    g_ntiles;
__device__ int    g_ticket;
__device__ int    g_done;

// ---------------- helpers ----------------
__device__ __forceinline__ uint32_t smem_u32(const void* p) {
    uint32_t a;
    asm("{ .reg .u64 t; cvta.to.shared.u64 t, %1; cvt.u32.u64 %0, t; }"
        : "=r"(a) : "l"(p));
    return a;
}
__device__ __forceinline__ void cpa16(uint32_t dst, const void* src, int sz) {
    asm volatile("cp.async.ca.shared.global [%0], [%1], 16, %2;"
                 :: "r"(dst), "l"(src), "r"(sz) : "memory");
}
#define CP_COMMIT() asm volatile("cp.async.commit_group;" ::: "memory")
#define CP_WAIT(n)  asm volatile("cp.async.wait_group %0;" :: "n"(n) : "memory")
#define MMAH(d, a0, a1, a2, a3, b0, b1)                                       \
    asm volatile(                                                             \
        "mma.sync.aligned.m16n8k16.row.col.f32.f16.f16.f32 "                  \
        "{%0,%1,%2,%3}, {%4,%5,%6,%7}, {%8,%9}, {%0,%1,%2,%3};"               \
        : "+f"((d)[0]), "+f"((d)[1]), "+f"((d)[2]), "+f"((d)[3])              \
        : "r"(a0), "r"(a1), "r"(a2), "r"(a3), "r"(b0), "r"(b1))
#define LDM4(R, addr)                                                         \
    asm volatile("ldmatrix.sync.aligned.m8n8.x4.shared.b16 {%0,%1,%2,%3}, [%4];" \
        : "=r"((R)[0]), "=r"((R)[1]), "=r"((R)[2]), "=r"((R)[3])              \
        : "r"(addr))
#define LDM4T(R, addr)                                                        \
    asm volatile("ldmatrix.sync.aligned.m8n8.x4.trans.shared.b16 {%0,%1,%2,%3}, [%4];" \
        : "=r"((R)[0]), "=r"((R)[1]), "=r"((R)[2]), "=r"((R)[3])              \
        : "r"(addr))

// ---------------- prep: fp32 -> fp16 (no transpose), zero counters --------
__global__ void prep_kernel(const float* __restrict__ x,
                            const float* __restrict__ wg,
                            const float* __restrict__ wu,
                            const float* __restrict__ wd) {
    int sel = blockIdx.z;
    if (sel == 3) {
        if (blockIdx.x == 0 && blockIdx.y == 0 && threadIdx.x < 34) {
            if (threadIdx.x < 32) g_cnt[threadIdx.x] = 0;
            else if (threadIdx.x == 32) g_done = 0;
            else g_ticket = 0;
        }
        size_t i = ((size_t)blockIdx.y * gridDim.x + blockIdx.x) * blockDim.x +
                   threadIdx.x;
        if (i < (size_t)T_TOKENS * HDIM / 2) {
            float2 f = ((const float2*)x)[i];
            ((__half2*)g_xh)[i] = __floats2half2_rn(f.x, f.y);
        }
        return;
    }
    // weights: straight convert, same layout. per (sel, e): 2^19 floats = 2^18 float2
    int e = blockIdx.y;
    const float2* src = (const float2*)(((sel == 0) ? wg : (sel == 1) ? wu : wd) +
                                        (size_t)e * HDIM * IDIM);
    __half2* dst = (__half2*)(((sel == 0) ? g_wgh : (sel == 1) ? g_wuh : g_wdh) +
                              (size_t)e * HDIM * IDIM);
    int i = blockIdx.x * blockDim.x + threadIdx.x;
    float2 f = src[i];
    dst[i] = __floats2half2_rn(f.x, f.y);
}

// ---------------- router: logits -> top-4 ----------------
__global__ void router_kernel(const float* __restrict__ x,
                              const float* __restrict__ gw) {
    __shared__ float xs[8][HDIM];
    int t0 = blockIdx.x * 8;
    for (int i = threadIdx.x; i < 8 * (HDIM / 4); i += blockDim.x) {
        int row = i >> 8;
        int c4  = i & 255;
        ((float4*)xs[row])[c4] = ((const float4*)(x + (size_t)(t0 + row) * HDIM))[c4];
    }
    __syncthreads();

    int w = threadIdx.x >> 5;
    int lane = threadIdx.x & 31;
    int t = t0 + w;
    const float* xr = xs[w];

    float myLogit = 0.f;
    for (int e = 0; e < NEXP; ++e) {
        const float* wr = gw + (size_t)e * HDIM;
        float s = 0.f;
        #pragma unroll 8
        for (int j = lane; j < HDIM; j += 32) s += xr[j] * wr[j];
        #pragma unroll
        for (int off = 16; off; off >>= 1) s += __shfl_xor_sync(0xffffffffu, s, off);
        if (lane == e) myLogit = s;
    }

    float v = myLogit;
    float selv[TOPK];
    int   seli[TOPK];
    #pragma unroll
    for (int k = 0; k < TOPK; ++k) {
        float bv = v; int bi = lane;
        #pragma unroll
        for (int off = 16; off; off >>= 1) {
            float ov = __shfl_xor_sync(0xffffffffu, bv, off);
            int   oi = __shfl_xor_sync(0xffffffffu, bi, off);
            if (ov > bv || (ov == bv && oi < bi)) { bv = ov; bi = oi; }
        }
        selv[k] = bv; seli[k] = bi;
        if (lane == bi) v = -1e30f;
    }

    if (lane == 0) {
        float m = selv[0];
        float ew[TOPK];
        float sum = 0.f;
        #pragma unroll
        for (int k = 0; k < TOPK; ++k) { ew[k] = expf(selv[k] - m); sum += ew[k]; }
        float inv = 1.f / sum;
        #pragma unroll
        for (int k = 0; k < TOPK; ++k) {
            g_top_idx[t * TOPK + k] = seli[k];
            g_top_wt [t * TOPK + k] = ew[k] * inv;
        }
    }
}

// ---------------- scatter + last-block prefix/tile-list ----------------
__global__ void scatter_prefix_kernel() {
    int t = blockIdx.x * blockDim.x + threadIdx.x;
    if (t < T_TOKENS) {
        #pragma unroll
        for (int k = 0; k < TOPK; ++k) {
            int e = g_top_idx[t * TOPK + k];
            int pos = atomicAdd(&g_cnt[e], 1);
            g_etok[e * T_TOKENS + pos] = (t << 2) | k;
            g_ewt [e * T_TOKENS + pos] = g_top_wt[t * TOPK + k];
        }
    }
    __threadfence();
    __syncthreads();
    if (threadIdx.x == 0) {
        int d = atomicAdd(&g_done, 1);
        if (d == (int)gridDim.x - 1) {
            int a = 0, nt = 0;
            for (int e = 0; e < NEXP; ++e) {
                g_off[e] = a;
                int c = *(volatile int*)&g_cnt[e];
                a += c;
                int nt_e = (c + TILE_M - 1) / TILE_M;
                for (int q = 0; q < nt_e; ++q) g_tiles[nt++] = (e << 16) | q;
            }
            g_ntiles = nt;
            g_ticket = 0;
            __threadfence();
        }
    }
}

// ---------------- expert: fp16 mma + trans-ldmatrix B + 3-stage cp.async ----
__global__ void __launch_bounds__(256, 2)
expert_mma() {
    extern __shared__ char sm[];
    __shared__ int   s_tok[TILE_M];
    __shared__ int   s_slot[TILE_M];
    __shared__ float s_wt[TILE_M];
    __shared__ int   s_tile;

    uint32_t smb = smem_u32(sm);
    int tid = threadIdx.x;
    int wid = tid >> 5, lane = tid & 31;
    int gr = lane >> 2, tig = lane & 3;
    int m0 = (wid & 3) * 32;
    int gsel = wid >> 2;
    int n0a = gsel * 32;
    int n0b = gsel * 64;

    // A (row-major [m][k], 144B rows): lanes 0-15 rows, k-halves via bit4
    uint32_t aoff = (uint32_t)(m0 + (lane & 15)) * 144 + ((lane >> 4) & 1) * 16;
    // B (k-major [k][n] rows), trans-ldmatrix: lanes 0-15 k-rows, n-halves via bit4
    uint32_t tk = (uint32_t)(lane & 15);
    uint32_t tn = ((lane >> 4) & 1) * 16;
    uint32_t gboff = (uint32_t)WG_OFF + tk * 144 + (uint32_t)n0a * 2 + tn;
    uint32_t uboff = (uint32_t)WU_OFF + tk * 144 + (uint32_t)n0a * 2 + tn;
    uint32_t dboff = (uint32_t)WD_OFF + tk * 272 + (uint32_t)n0b * 2 + tn;

    for (;;) {
        __syncthreads();
        if (tid == 0) s_tile = atomicAdd(&g_ticket, 1);
        __syncthreads();
        int tI = s_tile;
        if (tI >= g_ntiles) return;
        int pk_t = g_tiles[tI];
        int e = pk_t >> 16;
        int start = (pk_t & 0xffff) * TILE_M;
        int cnt = g_cnt[e];
        int rows = min(TILE_M, cnt - start);

        if (tid < TILE_M) {
            if (tid < rows) {
                int pk = g_etok[e * T_TOKENS + start + tid];
                s_tok[tid] = pk >> 2; s_slot[tid] = pk & 3;
                s_wt[tid] = g_ewt[e * T_TOKENS + start + tid];
            } else { s_tok[tid] = 0; s_slot[tid] = 0; s_wt[tid] = 0.f; }
        }
        __syncthreads();

        const __half* wghE = g_wgh + (size_t)e * HDIM * IDIM;
        const __half* wuhE = g_wuh + (size_t)e * HDIM * IDIM;
        const __half* wdhE = g_wdh + (size_t)e * HDIM * IDIM;
        int hbase = g_off[e] + start;

        // ============== Phase A: h = silu(x Wg) * (x Wu) ==============
        for (int nb = 0; nb < IDIM / 64; ++nb) {
            float accg[2][4][4], accu[2][4][4];
            #pragma unroll
            for (int i = 0; i < 2; ++i)
                #pragma unroll
                for (int j = 0; j < 4; ++j)
                    #pragma unroll
                    for (int q = 0; q < 4; ++q) { accg[i][j][q] = 0.f; accu[i][j][q] = 0.f; }

            // stage: X [128m x 64k] rows 144B; Wg/Wu [64k x 64n] rows 144B
            #define STAGE_A(c)  do {                                               \
                uint32_t sb = smb + ((c) % NSTAGE) * STAGE;                        \
                int k0 = (c) * KC;                                                 \
                _Pragma("unroll")                                                  \
                for (int i2 = 0; i2 < 4; ++i2) {                                   \
                    int idx = tid + i2 * 256;                                      \
                    int m = idx >> 3, seg = idx & 7;                               \
                    cpa16(sb + m * 144 + seg * 16,                                 \
                          g_xh + (size_t)s_tok[m] * HDIM + k0 + seg * 8,           \
                          (m < rows) ? 16 : 0);                                    \
                }                                                                  \
                _Pragma("unroll")                                                  \
                for (int i2 = 0; i2 < 2; ++i2) {                                   \
                    int idx = tid + i2 * 256;                                      \
                    int kk = idx >> 3, seg = idx & 7;                              \
                    cpa16(sb + WG_OFF + kk * 144 + seg * 16,                       \
                          wghE + (size_t)(k0 + kk) * IDIM + nb * 64 + seg * 8, 16);\
                    cpa16(sb + WU_OFF + kk * 144 + seg * 16,                       \
                          wuhE + (size_t)(k0 + kk) * IDIM + nb * 64 + seg * 8, 16);\
                }                                                                  \
                CP_COMMIT();                                                       \
            } while (0)

            STAGE_A(0);
            STAGE_A(1);
            for (int c = 0; c < HDIM / KC; ++c) {
                CP_WAIT(1);
                __syncthreads();
                uint32_t sb = smb + (c % NSTAGE) * STAGE;
                #pragma unroll
                for (int ks = 0; ks < 4; ++ks) {
                    // load ALL fragments for this ks first, then all MMAs
                    uint32_t a0[4], a1[4], bg0[4], bg1[4], bu0[4], bu1[4];
                    LDM4(a0, sb + aoff + ks * 32);
                    LDM4(a1, sb + aoff + 2304 + ks * 32);
                    LDM4T(bg0, sb + gboff + ks * 2304);
                    LDM4T(bg1, sb + gboff + ks * 2304 + 32);
                    LDM4T(bu0, sb + uboff + ks * 2304);
                    LDM4T(bu1, sb + uboff + ks * 2304 + 32);
                    MMAH(accg[0][0], a0[0], a0[1], a0[2], a0[3], bg0[0], bg0[1]);
                    MMAH(accg[1][0], a1[0], a1[1], a1[2], a1[3], bg0[0], bg0[1]);
                    MMAH(accg[0][1], a0[0], a0[1], a0[2], a0[3], bg0[2], bg0[3]);
                    MMAH(accg[1][1], a1[0], a1[1], a1[2], a1[3], bg0[2], bg0[3]);
                    MMAH(accg[0][2], a0[0], a0[1], a0[2], a0[3], bg1[0], bg1[1]);
                    MMAH(accg[1][2], a1[0], a1[1], a1[2], a1[3], bg1[0], bg1[1]);
                    MMAH(accg[0][3], a0[0], a0[1], a0[2], a0[3], bg1[2], bg1[3]);
                    MMAH(accg[1][3], a1[0], a1[1], a1[2], a1[3], bg1[2], bg1[3]);
                    MMAH(accu[0][0], a0[0], a0[1], a0[2], a0[3], bu0[0], bu0[1]);
                    MMAH(accu[1][0], a1[0], a1[1], a1[2], a1[3], bu0[0], bu0[1]);
                    MMAH(accu[0][1], a0[0], a0[1], a0[2], a0[3], bu0[2], bu0[3]);
                    MMAH(accu[1][1], a1[0], a1[1], a1[2], a1[3], bu0[2], bu0[3]);
                    MMAH(accu[0][2], a0[0], a0[1], a0[2], a0[3], bu1[0], bu1[1]);
                    MMAH(accu[1][2], a1[0], a1[1], a1[2], a1[3], bu1[0], bu1[1]);
                    MMAH(accu[0][3], a0[0], a0[1], a0[2], a0[3], bu1[2], bu1[3]);
                    MMAH(accu[1][3], a1[0], a1[1], a1[2], a1[3], bu1[2], bu1[3]);
                }
                if (c + 2 < HDIM / KC) STAGE_A(c + 2);
                else CP_COMMIT();
            }
            #undef STAGE_A

            // epilogue: silu(gate)*up -> g_hh (fp16)
            #pragma unroll
            for (int i = 0; i < 2; ++i) {
                #pragma unroll
                for (int half = 0; half < 2; ++half) {
                    int m = m0 + 16 * i + gr + 8 * half;
                    if (m < rows) {
                        __half* hp = g_hh + (size_t)(hbase + m) * IDIM + nb * 64 + n0a;
                        #pragma unroll
                        for (int j = 0; j < 4; ++j) {
                            float g0 = accg[i][j][half * 2 + 0];
                            float g1 = accg[i][j][half * 2 + 1];
                            float u0 = accu[i][j][half * 2 + 0];
                            float u1 = accu[i][j][half * 2 + 1];
                            float h0 = u0 * g0 / (1.f + __expf(-g0));
                            float h1 = u1 * g1 / (1.f + __expf(-g1));
                            *(__half2*)(hp + 8 * j + 2 * tig) = __floats2half2_rn(h0, h1);
                        }
                    }
                }
            }
            __syncthreads();
        }

        // ============== Phase B: y = (h Wd) * route_w ==============
        for (int nb = 0; nb < HDIM / 128; ++nb) {
            float acc[2][8][4];
            #pragma unroll
            for (int i = 0; i < 2; ++i)
                #pragma unroll
                for (int j = 0; j < 8; ++j)
                    #pragma unroll
                    for (int q = 0; q < 4; ++q) acc[i][j][q] = 0.f;

            // stage: h [128m x 64k] rows 144B; Wd [64k x 128n] rows 272B
            #define STAGE_B(c)  do {                                               \
                uint32_t sb = smb + ((c) % NSTAGE) * STAGE;                        \
                int k0 = (c) * KC;                                                 \
                _Pragma("unroll")                                                  \
                for (int i2 = 0; i2 < 4; ++i2) {                                   \
                    int idx = tid + i2 * 256;                                      \
                    int m = idx >> 3, seg = idx & 7;                               \
                    cpa16(sb + m * 144 + seg * 16,                                 \
                          g_hh + (size_t)(hbase + m) * IDIM + k0 + seg * 8,        \
                          (m < rows) ? 16 : 0);                                    \
                }                                                                  \
                _Pragma("unroll")                                                  \
                for (int i2 = 0; i2 < 4; ++i2) {                                   \
                    int idx = tid + i2 * 256;                                      \
                    int kk = idx >> 4, seg = idx & 15;                             \
                    cpa16(sb + WD_OFF + kk * 272 + seg * 16,                       \
                          wdhE + (size_t)(k0 + kk) * HDIM + nb * 128 + seg * 8, 16);\
                }                                                                  \
                CP_COMMIT();                                                       \
            } while (0)

            STAGE_B(0);
            STAGE_B(1);
            for (int c = 0; c < IDIM / KC; ++c) {
                CP_WAIT(1);
                __syncthreads();
                uint32_t sb = smb + (c % NSTAGE) * STAGE;
                #pragma unroll
                for (int ks = 0; ks < 4; ++ks) {
                    uint32_t a0[4], a1[4], b0[4], b1[4], b2[4], b3[4];
                    LDM4(a0, sb + aoff + ks * 32);
                    LDM4(a1, sb + aoff + 2304 + ks * 32);
                    LDM4T(b0, sb + dboff + ks * 4352);
                    LDM4T(b1, sb + dboff + ks * 4352 + 32);
                    LDM4T(b2, sb + dboff + ks * 4352 + 64);
                    LDM4T(b3, sb + dboff + ks * 4352 + 96);
                    MMAH(acc[0][0], a0[0], a0[1], a0[2], a0[3], b0[0], b0[1]);
                    MMAH(acc[1][0], a1[0], a1[1], a1[2], a1[3], b0[0], b0[1]);
                    MMAH(acc[0][1], a0[0], a0[1], a0[2], a0[3], b0[2], b0[3]);
                    MMAH(acc[1][1], a1[0], a1[1], a1[2], a1[3], b0[2], b0[3]);
                    MMAH(acc[0][2], a0[0], a0[1], a0[2], a0[3], b1[0], b1[1]);
                    MMAH(acc[1][2], a1[0], a1[1], a1[2], a1[3], b1[0], b1[1]);
                    MMAH(acc[0][3], a0[0], a0[1], a0[2], a0[3], b1[2], b1[3]);
                    MMAH(acc[1][3], a1[0], a1[1], a1[2], a1[3], b1[2], b1[3]);
                    MMAH(acc[0][4], a0[0], a0[1], a0[2], a0[3], b2[0], b2[1]);
                    MMAH(acc[1][4], a1[0], a1[1], a1[2], a1[3], b2[0], b2[1]);
                    MMAH(acc[0][5], a0[0], a0[1], a0[2], a0[3], b2[2], b2[3]);
                    MMAH(acc[1][5], a1[0], a1[1], a1[2], a1[3], b2[2], b2[3]);
                    MMAH(acc[0][6], a0[0], a0[1], a0[2], a0[3], b3[0], b3[1]);
                    MMAH(acc[1][6], a1[0], a1[1], a1[2], a1[3], b3[0], b3[1]);
                    MMAH(acc[0][7], a0[0], a0[1], a0[2], a0[3], b3[2], b3[3]);
                    MMAH(acc[1][7], a1[0], a1[1], a1[2], a1[3], b3[2], b3[3]);
                }
                if (c + 2 < IDIM / KC) STAGE_B(c + 2);
                else CP_COMMIT();
            }
            #undef STAGE_B

            // epilogue: apply routing weight, write fp32 partials
            #pragma unroll
            for (int i = 0; i < 2; ++i) {
                #pragma unroll
                for (int half = 0; half < 2; ++half) {
                    int m = m0 + 16 * i + gr + 8 * half;
                    if (m < rows) {
                        float wgt = s_wt[m];
                        float* dp = g_partial +
                            ((size_t)s_tok[m] * TOPK + s_slot[m]) * HDIM + nb * 128 + n0b;
                        #pragma unroll
                        for (int j = 0; j < 8; ++j) {
                            float y0 = wgt * acc[i][j][half * 2 + 0];
                            float y1 = wgt * acc[i][j][half * 2 + 1];
                            *(float2*)(dp + 8 * j + 2 * tig) = make_float2(y0, y1);
                        }
                    }
                }
            }
            __syncthreads();
        }
    }
}

// ---------------- combine: out[t][h] = sum_k partial[t][k][h] -------------
__global__ void combine_kernel(float* __restrict__ out) {
    size_t i = (size_t)blockIdx.x * blockDim.x + threadIdx.x;
    const float4* s = (const float4*)g_partial;
    size_t t = i >> 8;
    size_t c = i & 255;
    size_t base = t * (TOPK * 256) + c;
    float4 a = s[base], b = s[base + 256], cc = s[base + 512], d = s[base + 768];
    ((float4*)out)[i] = make_float4(a.x + b.x + cc.x + d.x,
                                    a.y + b.y + cc.y + d.y,
                                    a.z + b.z + cc.z + d.z,
                                    a.w + b.w + cc.w + d.w);
}

// ---------------- launch ---------------------------------------------------
extern "C" void kernel_launch(void* const* d_in, const int* in_sizes, int n_in,
                              void* d_out, int out_size) {
    const float* x  = (const float*)d_in[0];
    const float* gw = (const float*)d_in[1];
    const float* wg = (const float*)d_in[2];
    const float* wu = (const float*)d_in[3];
    const float* wd = (const float*)d_in[4];
    float* out = (float*)d_out;

    // sel 0..2: per-expert weight convert (1024 blocks x 256 = 2^18 float2)
    // sel 3:    x convert (bounded) + counter zeroing
    prep_kernel<<<dim3(1024, NEXP, 4), 256>>>(x, wg, wu, wd);
    router_kernel<<<T_TOKENS / 8, 256>>>(x, gw);
    scatter_prefix_kernel<<<T_TOKENS / 256, 256>>>();

    int smem = NSTAGE * STAGE;
    cudaFuncSetAttribute(expert_mma,
                         cudaFuncAttributeMaxDynamicSharedMemorySize, smem);
    expert_mma<<<296, 256, smem>>>();

    combine_kernel<<<(T_TOKENS * HDIM / 4) / 256, 256>>>(out);
}

// round 15
// speedup vs baseline: 1.0550x; 1.0550x over previous
#include <cuda_runtime.h>
#include <cuda_fp16.h>
#include <math.h>
#include <stdint.h>

#define T_TOKENS 8192
#define HDIM 1024
#define IDIM 512
#define NEXP 32
#define TOPK 4
#define TILE_M 128
#define KC 64
#define STAGE 36864            // bytes per pipeline stage
#define NSTAGE 3
#define WG_OFF 18432           // Phase A: A[128x144B], Wg[64x144B], Wu[64x144B]
#define WU_OFF 27648
#define WD_OFF 18432           // Phase B: A[128x144B], Wd[64x272B]

// ---------------- device scratch ----------------
__device__ float  g_partial[(size_t)T_TOKENS * TOPK * HDIM];   // 128 MB fp32
__device__ __half g_hh[(size_t)T_TOKENS * TOPK * IDIM];        // 32 MB
__device__ __half g_xh[(size_t)T_TOKENS * HDIM];               // 16 MB
__device__ __half g_wgh[(size_t)NEXP * HDIM * IDIM];           // 32 MB [E][H][I] (k-major)
__device__ __half g_wuh[(size_t)NEXP * HDIM * IDIM];           // 32 MB [E][H][I]
__device__ __half g_wdh[(size_t)NEXP * IDIM * HDIM];           // 32 MB [E][I][H] (k-major)
__device__ int    g_top_idx[T_TOKENS * TOPK];
__device__ float  g_top_wt [T_TOKENS * TOPK];
__device__ int    g_cnt[NEXP];
__device__ int    g_off[NEXP];
__device__ int    g_etok[NEXP * T_TOKENS];
__device__ float  g_ewt [NEXP * T_TOKENS];
__device__ int    g_tiles[2048];
__device__ int    g_ntiles;
__device__ int    g_ticket;
__device__ int    g_done;

// ---------------- helpers ----------------
__device__ __forceinline__ uint32_t smem_u32(const void* p) {
    uint32_t a;
    asm("{ .reg .u64 t; cvta.to.shared.u64 t, %1; cvt.u32.u64 %0, t; }"
        : "=r"(a) : "l"(p));
    return a;
}
__device__ __forceinline__ void cpa16(uint32_t dst, const void* src, int sz) {
    asm volatile("cp.async.ca.shared.global [%0], [%1], 16, %2;"
                 :: "r"(dst), "l"(src), "r"(sz) : "memory");
}
#define CP_COMMIT() asm volatile("cp.async.commit_group;" ::: "memory")
#define CP_WAIT(n)  asm volatile("cp.async.wait_group %0;" :: "n"(n) : "memory")
#define MMAH(d, a0, a1, a2, a3, b0, b1)                                       \
    asm volatile(                                                             \
        "mma.sync.aligned.m16n8k16.row.col.f32.f16.f16.f32 "                  \
        "{%0,%1,%2,%3}, {%4,%5,%6,%7}, {%8,%9}, {%0,%1,%2,%3};"               \
        : "+f"((d)[0]), "+f"((d)[1]), "+f"((d)[2]), "+f"((d)[3])              \
        : "r"(a0), "r"(a1), "r"(a2), "r"(a3), "r"(b0), "r"(b1))
#define LDM4(R, addr)                                                         \
    asm volatile("ldmatrix.sync.aligned.m8n8.x4.shared.b16 {%0,%1,%2,%3}, [%4];" \
        : "=r"((R)[0]), "=r"((R)[1]), "=r"((R)[2]), "=r"((R)[3])              \
        : "r"(addr))
#define LDM4T(R, addr)                                                        \
    asm volatile("ldmatrix.sync.aligned.m8n8.x4.trans.shared.b16 {%0,%1,%2,%3}, [%4];" \
        : "=r"((R)[0]), "=r"((R)[1]), "=r"((R)[2]), "=r"((R)[3])              \
        : "r"(addr))

// ---------------- prep: fused fp32->fp16 convert (grid-stride, float4) ------
__global__ void prep_kernel(const float* __restrict__ x,
                            const float* __restrict__ wg,
                            const float* __restrict__ wu,
                            const float* __restrict__ wd) {
    if (blockIdx.x == 0 && threadIdx.x < 34) {
        if (threadIdx.x < 32) g_cnt[threadIdx.x] = 0;
        else if (threadIdx.x == 32) g_done = 0;
        else g_ticket = 0;
    }
    const size_t W4 = (size_t)NEXP * HDIM * IDIM / 4;      // float4 units per weight
    const size_t X4 = (size_t)T_TOKENS * HDIM / 4;
    const size_t total = 3 * W4 + X4;
    size_t stride = (size_t)gridDim.x * blockDim.x;
    for (size_t i = (size_t)blockIdx.x * blockDim.x + threadIdx.x;
         i < total; i += stride) {
        const float4* src;
        __half2* dst;
        size_t off;
        if (i < W4)            { src = (const float4*)wg; dst = (__half2*)g_wgh; off = i; }
        else if (i < 2 * W4)   { src = (const float4*)wu; dst = (__half2*)g_wuh; off = i - W4; }
        else if (i < 3 * W4)   { src = (const float4*)wd; dst = (__half2*)g_wdh; off = i - 2 * W4; }
        else                   { src = (const float4*)x;  dst = (__half2*)g_xh;  off = i - 3 * W4; }
        float4 f = src[off];
        dst[2 * off]     = __floats2half2_rn(f.x, f.y);
        dst[2 * off + 1] = __floats2half2_rn(f.z, f.w);
    }
}

// ---------------- router: logits -> top-4 ----------------
__global__ void router_kernel(const float* __restrict__ x,
                              const float* __restrict__ gw) {
    __shared__ float xs[8][HDIM];
    int t0 = blockIdx.x * 8;
    for (int i = threadIdx.x; i < 8 * (HDIM / 4); i += blockDim.x) {
        int row = i >> 8;
        int c4  = i & 255;
        ((float4*)xs[row])[c4] = ((const float4*)(x + (size_t)(t0 + row) * HDIM))[c4];
    }
    __syncthreads();

    int w = threadIdx.x >> 5;
    int lane = threadIdx.x & 31;
    int t = t0 + w;
    const float* xr = xs[w];

    float myLogit = 0.f;
    for (int e = 0; e < NEXP; ++e) {
        const float* wr = gw + (size_t)e * HDIM;
        float s = 0.f;
        #pragma unroll 8
        for (int j = lane; j < HDIM; j += 32) s += xr[j] * wr[j];
        #pragma unroll
        for (int off = 16; off; off >>= 1) s += __shfl_xor_sync(0xffffffffu, s, off);
        if (lane == e) myLogit = s;
    }

    float v = myLogit;
    float selv[TOPK];
    int   seli[TOPK];
    #pragma unroll
    for (int k = 0; k < TOPK; ++k) {
        float bv = v; int bi = lane;
        #pragma unroll
        for (int off = 16; off; off >>= 1) {
            float ov = __shfl_xor_sync(0xffffffffu, bv, off);
            int   oi = __shfl_xor_sync(0xffffffffu, bi, off);
            if (ov > bv || (ov == bv && oi < bi)) { bv = ov; bi = oi; }
        }
        selv[k] = bv; seli[k] = bi;
        if (lane == bi) v = -1e30f;
    }

    if (lane == 0) {
        float m = selv[0];
        float ew[TOPK];
        float sum = 0.f;
        #pragma unroll
        for (int k = 0; k < TOPK; ++k) { ew[k] = expf(selv[k] - m); sum += ew[k]; }
        float inv = 1.f / sum;
        #pragma unroll
        for (int k = 0; k < TOPK; ++k) {
            g_top_idx[t * TOPK + k] = seli[k];
            g_top_wt [t * TOPK + k] = ew[k] * inv;
        }
    }
}

// ---------------- scatter + last-block prefix/tile-list ----------------
__global__ void scatter_prefix_kernel() {
    int t = blockIdx.x * blockDim.x + threadIdx.x;
    if (t < T_TOKENS) {
        #pragma unroll
        for (int k = 0; k < TOPK; ++k) {
            int e = g_top_idx[t * TOPK + k];
            int pos = atomicAdd(&g_cnt[e], 1);
            g_etok[e * T_TOKENS + pos] = (t << 2) | k;
            g_ewt [e * T_TOKENS + pos] = g_top_wt[t * TOPK + k];
        }
    }
    __threadfence();
    __syncthreads();
    if (threadIdx.x == 0) {
        int d = atomicAdd(&g_done, 1);
        if (d == (int)gridDim.x - 1) {
            int a = 0, nt = 0;
            for (int e = 0; e < NEXP; ++e) {
                g_off[e] = a;
                int c = *(volatile int*)&g_cnt[e];
                a += c;
                int nt_e = (c + TILE_M - 1) / TILE_M;
                for (int q = 0; q < nt_e; ++q) g_tiles[nt++] = (e << 16) | q;
            }
            g_ntiles = nt;
            g_ticket = 0;
            __threadfence();
        }
    }
}

// ---------------- expert: fp16 mma + trans-ldmatrix B + 3-stage cp.async ----
__global__ void __launch_bounds__(256, 2)
expert_mma() {
    extern __shared__ char sm[];
    __shared__ int   s_tok[TILE_M];
    __shared__ int   s_slot[TILE_M];
    __shared__ float s_wt[TILE_M];
    __shared__ int   s_tile;

    uint32_t smb = smem_u32(sm);
    int tid = threadIdx.x;
    int wid = tid >> 5, lane = tid & 31;
    int gr = lane >> 2, tig = lane & 3;
    int m0 = (wid & 3) * 32;
    int gsel = wid >> 2;
    int n0a = gsel * 32;
    int n0b = gsel * 64;

    // A (row-major [m][k], 144B rows): lanes 0-15 rows, k-halves via bit4
    uint32_t aoff = (uint32_t)(m0 + (lane & 15)) * 144 + ((lane >> 4) & 1) * 16;
    // B (k-major [k][n] rows), trans-ldmatrix: lanes 0-15 k-rows, n-halves via bit4
    uint32_t tk = (uint32_t)(lane & 15);
    uint32_t tn = ((lane >> 4) & 1) * 16;
    uint32_t gboff = (uint32_t)WG_OFF + tk * 144 + (uint32_t)n0a * 2 + tn;
    uint32_t uboff = (uint32_t)WU_OFF + tk * 144 + (uint32_t)n0a * 2 + tn;
    uint32_t dboff = (uint32_t)WD_OFF + tk * 272 + (uint32_t)n0b * 2 + tn;

    for (;;) {
        __syncthreads();
        if (tid == 0) s_tile = atomicAdd(&g_ticket, 1);
        __syncthreads();
        int tI = s_tile;
        if (tI >= g_ntiles) return;
        int pk_t = g_tiles[tI];
        int e = pk_t >> 16;
        int start = (pk_t & 0xffff) * TILE_M;
        int cnt = g_cnt[e];
        int rows = min(TILE_M, cnt - start);

        if (tid < TILE_M) {
            if (tid < rows) {
                int pk = g_etok[e * T_TOKENS + start + tid];
                s_tok[tid] = pk >> 2; s_slot[tid] = pk & 3;
                s_wt[tid] = g_ewt[e * T_TOKENS + start + tid];
            } else { s_tok[tid] = 0; s_slot[tid] = 0; s_wt[tid] = 0.f; }
        }
        __syncthreads();

        const __half* wghE = g_wgh + (size_t)e * HDIM * IDIM;
        const __half* wuhE = g_wuh + (size_t)e * HDIM * IDIM;
        const __half* wdhE = g_wdh + (size_t)e * HDIM * IDIM;
        int hbase = g_off[e] + start;

        // ============== Phase A: h = silu(x Wg) * (x Wu) ==============
        for (int nb = 0; nb < IDIM / 64; ++nb) {
            float accg[2][4][4], accu[2][4][4];
            #pragma unroll
            for (int i = 0; i < 2; ++i)
                #pragma unroll
                for (int j = 0; j < 4; ++j)
                    #pragma unroll
                    for (int q = 0; q < 4; ++q) { accg[i][j][q] = 0.f; accu[i][j][q] = 0.f; }

            // stage: X [128m x 64k] rows 144B; Wg/Wu [64k x 64n] rows 144B
            #define STAGE_A(c)  do {                                               \
                uint32_t sb = smb + ((c) % NSTAGE) * STAGE;                        \
                int k0 = (c) * KC;                                                 \
                _Pragma("unroll")                                                  \
                for (int i2 = 0; i2 < 4; ++i2) {                                   \
                    int idx = tid + i2 * 256;                                      \
                    int m = idx >> 3, seg = idx & 7;                               \
                    cpa16(sb + m * 144 + seg * 16,                                 \
                          g_xh + (size_t)s_tok[m] * HDIM + k0 + seg * 8,           \
                          (m < rows) ? 16 : 0);                                    \
                }                                                                  \
                _Pragma("unroll")                                                  \
                for (int i2 = 0; i2 < 2; ++i2) {                                   \
                    int idx = tid + i2 * 256;                                      \
                    int kk = idx >> 3, seg = idx & 7;                              \
                    cpa16(sb + WG_OFF + kk * 144 + seg * 16,                       \
                          wghE + (size_t)(k0 + kk) * IDIM + nb * 64 + seg * 8, 16);\
                    cpa16(sb + WU_OFF + kk * 144 + seg * 16,                       \
                          wuhE + (size_t)(k0 + kk) * IDIM + nb * 64 + seg * 8, 16);\
                }                                                                  \
                CP_COMMIT();                                                       \
            } while (0)

            STAGE_A(0);
            STAGE_A(1);
            for (int c = 0; c < HDIM / KC; ++c) {
                CP_WAIT(1);
                __syncthreads();
                uint32_t sb = smb + (c % NSTAGE) * STAGE;
                #pragma unroll
                for (int ks = 0; ks < 4; ++ks) {
                    uint32_t a0[4], a1[4], bg0[4], bg1[4], bu0[4], bu1[4];
                    LDM4(a0, sb + aoff + ks * 32);
                    LDM4(a1, sb + aoff + 2304 + ks * 32);
                    LDM4T(bg0, sb + gboff + ks * 2304);
                    LDM4T(bg1, sb + gboff + ks * 2304 + 32);
                    LDM4T(bu0, sb + uboff + ks * 2304);
                    LDM4T(bu1, sb + uboff + ks * 2304 + 32);
                    MMAH(accg[0][0], a0[0], a0[1], a0[2], a0[3], bg0[0], bg0[1]);
                    MMAH(accg[1][0], a1[0], a1[1], a1[2], a1[3], bg0[0], bg0[1]);
                    MMAH(accg[0][1], a0[0], a0[1], a0[2], a0[3], bg0[2], bg0[3]);
                    MMAH(accg[1][1], a1[0], a1[1], a1[2], a1[3], bg0[2], bg0[3]);
                    MMAH(accg[0][2], a0[0], a0[1], a0[2], a0[3], bg1[0], bg1[1]);
                    MMAH(accg[1][2], a1[0], a1[1], a1[2], a1[3], bg1[0], bg1[1]);
                    MMAH(accg[0][3], a0[0], a0[1], a0[2], a0[3], bg1[2], bg1[3]);
                    MMAH(accg[1][3], a1[0], a1[1], a1[2], a1[3], bg1[2], bg1[3]);
                    MMAH(accu[0][0], a0[0], a0[1], a0[2], a0[3], bu0[0], bu0[1]);
                    MMAH(accu[1][0], a1[0], a1[1], a1[2], a1[3], bu0[0], bu0[1]);
                    MMAH(accu[0][1], a0[0], a0[1], a0[2], a0[3], bu0[2], bu0[3]);
                    MMAH(accu[1][1], a1[0], a1[1], a1[2], a1[3], bu0[2], bu0[3]);
                    MMAH(accu[0][2], a0[0], a0[1], a0[2], a0[3], bu1[0], bu1[1]);
                    MMAH(accu[1][2], a1[0], a1[1], a1[2], a1[3], bu1[0], bu1[1]);
                    MMAH(accu[0][3], a0[0], a0[1], a0[2], a0[3], bu1[2], bu1[3]);
                    MMAH(accu[1][3], a1[0], a1[1], a1[2], a1[3], bu1[2], bu1[3]);
                }
                if (c + 2 < HDIM / KC) STAGE_A(c + 2);
                else CP_COMMIT();
            }
            #undef STAGE_A

            // epilogue: silu(gate)*up -> g_hh (fp16)
            #pragma unroll
            for (int i = 0; i < 2; ++i) {
                #pragma unroll
                for (int half = 0; half < 2; ++half) {
                    int m = m0 + 16 * i + gr + 8 * half;
                    if (m < rows) {
                        __half* hp = g_hh + (size_t)(hbase + m) * IDIM + nb * 64 + n0a;
                        #pragma unroll
                        for (int j = 0; j < 4; ++j) {
                            float g0 = accg[i][j][half * 2 + 0];
                            float g1 = accg[i][j][half * 2 + 1];
                            float u0 = accu[i][j][half * 2 + 0];
                            float u1 = accu[i][j][half * 2 + 1];
                            float h0 = u0 * g0 / (1.f + __expf(-g0));
                            float h1 = u1 * g1 / (1.f + __expf(-g1));
                            *(__half2*)(hp + 8 * j + 2 * tig) = __floats2half2_rn(h0, h1);
                        }
                    }
                }
            }
            __syncthreads();
        }

        // ============== Phase B: y = (h Wd) * route_w ==============
        for (int nb = 0; nb < HDIM / 128; ++nb) {
            float acc[2][8][4];
            #pragma unroll
            for (int i = 0; i < 2; ++i)
                #pragma unroll
                for (int j = 0; j < 8; ++j)
                    #pragma unroll
                    for (int q = 0; q < 4; ++q) acc[i][j][q] = 0.f;

            // stage: h [128m x 64k] rows 144B; Wd [64k x 128n] rows 272B
            #define STAGE_B(c)  do {                                               \
                uint32_t sb = smb + ((c) % NSTAGE) * STAGE;                        \
                int k0 = (c) * KC;                                                 \
                _Pragma("unroll")                                                  \
                for (int i2 = 0; i2 < 4; ++i2) {                                   \
                    int idx = tid + i2 * 256;                                      \
                    int m = idx >> 3, seg = idx & 7;                               \
                    cpa16(sb + m * 144 + seg * 16,                                 \
                          g_hh + (size_t)(hbase + m) * IDIM + k0 + seg * 8,        \
                          (m < rows) ? 16 : 0);                                    \
                }                                                                  \
                _Pragma("unroll")                                                  \
                for (int i2 = 0; i2 < 4; ++i2) {                                   \
                    int idx = tid + i2 * 256;                                      \
                    int kk = idx >> 4, seg = idx & 15;                             \
                    cpa16(sb + WD_OFF + kk * 272 + seg * 16,                       \
                          wdhE + (size_t)(k0 + kk) * HDIM + nb * 128 + seg * 8, 16);\
                }                                                                  \
                CP_COMMIT();                                                       \
            } while (0)

            STAGE_B(0);
            STAGE_B(1);
            for (int c = 0; c < IDIM / KC; ++c) {
                CP_WAIT(1);
                __syncthreads();
                uint32_t sb = smb + (c % NSTAGE) * STAGE;
                #pragma unroll
                for (int ks = 0; ks < 4; ++ks) {
                    uint32_t a0[4], a1[4], b0[4], b1[4], b2[4], b3[4];
                    LDM4(a0, sb + aoff + ks * 32);
                    LDM4(a1, sb + aoff + 2304 + ks * 32);
                    LDM4T(b0, sb + dboff + ks * 4352);
                    LDM4T(b1, sb + dboff + ks * 4352 + 32);
                    LDM4T(b2, sb + dboff + ks * 4352 + 64);
                    LDM4T(b3, sb + dboff + ks * 4352 + 96);
                    MMAH(acc[0][0], a0[0], a0[1], a0[2], a0[3], b0[0], b0[1]);
                    MMAH(acc[1][0], a1[0], a1[1], a1[2], a1[3], b0[0], b0[1]);
                    MMAH(acc[0][1], a0[0], a0[1], a0[2], a0[3], b0[2], b0[3]);
                    MMAH(acc[1][1], a1[0], a1[1], a1[2], a1[3], b0[2], b0[3]);
                    MMAH(acc[0][2], a0[0], a0[1], a0[2], a0[3], b1[0], b1[1]);
                    MMAH(acc[1][2], a1[0], a1[1], a1[2], a1[3], b1[0], b1[1]);
                    MMAH(acc[0][3], a0[0], a0[1], a0[2], a0[3], b1[2], b1[3]);
                    MMAH(acc[1][3], a1[0], a1[1], a1[2], a1[3], b1[2], b1[3]);
                    MMAH(acc[0][4], a0[0], a0[1], a0[2], a0[3], b2[0], b2[1]);
                    MMAH(acc[1][4], a1[0], a1[1], a1[2], a1[3], b2[0], b2[1]);
                    MMAH(acc[0][5], a0[0], a0[1], a0[2], a0[3], b2[2], b2[3]);
                    MMAH(acc[1][5], a1[0], a1[1], a1[2], a1[3], b2[2], b2[3]);
                    MMAH(acc[0][6], a0[0], a0[1], a0[2], a0[3], b3[0], b3[1]);
                    MMAH(acc[1][6], a1[0], a1[1], a1[2], a1[3], b3[0], b3[1]);
                    MMAH(acc[0][7], a0[0], a0[1], a0[2], a0[3], b3[2], b3[3]);
                    MMAH(acc[1][7], a1[0], a1[1], a1[2], a1[3], b3[2], b3[3]);
                }
                if (c + 2 < IDIM / KC) STAGE_B(c + 2);
                else CP_COMMIT();
            }
            #undef STAGE_B

            // epilogue: apply routing weight, write fp32 partials
            #pragma unroll
            for (int i = 0; i < 2; ++i) {
                #pragma unroll
                for (int half = 0; half < 2; ++half) {
                    int m = m0 + 16 * i + gr + 8 * half;
                    if (m < rows) {
                        float wgt = s_wt[m];
                        float* dp = g_partial +
                            ((size_t)s_tok[m] * TOPK + s_slot[m]) * HDIM + nb * 128 + n0b;
                        #pragma unroll
                        for (int j = 0; j < 8; ++j) {
                            float y0 = wgt * acc[i][j][half * 2 + 0];
                            float y1 = wgt * acc[i][j][half * 2 + 1];
                            *(float2*)(dp + 8 * j + 2 * tig) = make_float2(y0, y1);
                        }
                    }
                }
            }
            __syncthreads();
        }
    }
}

// ---------------- combine: out[t][h] = sum_k partial[t][k][h] -------------
__global__ void combine_kernel(float* __restrict__ out) {
    size_t i = (size_t)blockIdx.x * blockDim.x + threadIdx.x;
    const float4* s = (const float4*)g_partial;
    size_t t = i >> 8;
    size_t c = i & 255;
    size_t base = t * (TOPK * 256) + c;
    float4 a = s[base], b = s[base + 256], cc = s[base + 512], d = s[base + 768];
    ((float4*)out)[i] = make_float4(a.x + b.x + cc.x + d.x,
                                    a.y + b.y + cc.y + d.y,
                                    a.z + b.z + cc.z + d.z,
                                    a.w + b.w + cc.w + d.w);
}

// ---------------- launch ---------------------------------------------------
extern "C" void kernel_launch(void* const* d_in, const int* in_sizes, int n_in,
                              void* d_out, int out_size) {
    const float* x  = (const float*)d_in[0];
    const float* gw = (const float*)d_in[1];
    const float* wg = (const float*)d_in[2];
    const float* wu = (const float*)d_in[3];
    const float* wd = (const float*)d_in[4];
    float* out = (float*)d_out;

    prep_kernel<<<4736, 256>>>(x, wg, wu, wd);
    router_kernel<<<T_TOKENS / 8, 256>>>(x, gw);
    scatter_prefix_kernel<<<T_TOKENS / 256, 256>>>();

    int smem = NSTAGE * STAGE;
    cudaFuncSetAttribute(expert_mma,
                         cudaFuncAttributeMaxDynamicSharedMemorySize, smem);
    expert_mma<<<296, 256, smem>>>();

    combine_kernel<<<(T_TOKENS * HDIM / 4) / 256, 256>>>(out);
}

// round 16
// speedup vs baseline: 1.1012x; 1.0438x over previous
#include <cuda_runtime.h>
#include <cuda_fp16.h>
#include <math.h>
#include <stdint.h>

#define T_TOKENS 8192
#define HDIM 1024
#define IDIM 512
#define NEXP 32
#define TOPK 4
#define TILE_M 128
#define KC 64
#define STAGE 36864            // bytes per pipeline stage
#define NSTAGE 3
#define WG_OFF 18432           // Phase A: A[128x144B], Wg[64x144B], Wu[64x144B]
#define WU_OFF 27648
#define WD_OFF 18432           // Phase B: A[128x144B], Wd[64x272B]
#define ROUTER_BLOCKS 1024

// ---------------- device scratch ----------------
__device__ __half g_partial[(size_t)T_TOKENS * TOPK * HDIM];   // 64 MB fp16
__device__ __half g_hh[(size_t)T_TOKENS * TOPK * IDIM];        // 32 MB
__device__ __half g_xh[(size_t)T_TOKENS * HDIM];               // 16 MB
__device__ __half g_wgh[(size_t)NEXP * HDIM * IDIM];           // 32 MB [E][H][I] (k-major)
__device__ __half g_wuh[(size_t)NEXP * HDIM * IDIM];           // 32 MB [E][H][I]
__device__ __half g_wdh[(size_t)NEXP * IDIM * HDIM];           // 32 MB [E][I][H] (k-major)
__device__ int    g_top_idx[T_TOKENS * TOPK];
__device__ float  g_top_wt [T_TOKENS * TOPK];
__device__ int    g_cnt[NEXP];
__device__ int    g_off[NEXP];
__device__ int    g_etok[NEXP * T_TOKENS];
__device__ float  g_ewt [NEXP * T_TOKENS];
__device__ int    g_tiles[2048];
__device__ int    g_ntiles;
__device__ int    g_ticket;
__device__ int    g_done;

// ---------------- helpers ----------------
__device__ __forceinline__ uint32_t smem_u32(const void* p) {
    uint32_t a;
    asm("{ .reg .u64 t; cvta.to.shared.u64 t, %1; cvt.u32.u64 %0, t; }"
        : "=r"(a) : "l"(p));
    return a;
}
__device__ __forceinline__ void cpa16(uint32_t dst, const void* src, int sz) {
    asm volatile("cp.async.ca.shared.global [%0], [%1], 16, %2;"
                 :: "r"(dst), "l"(src), "r"(sz) : "memory");
}
#define CP_COMMIT() asm volatile("cp.async.commit_group;" ::: "memory")
#define CP_WAIT(n)  asm volatile("cp.async.wait_group %0;" :: "n"(n) : "memory")
#define MMAH(d, a0, a1, a2, a3, b0, b1)                                       \
    asm volatile(                                                             \
        "mma.sync.aligned.m16n8k16.row.col.f32.f16.f16.f32 "                  \
        "{%0,%1,%2,%3}, {%4,%5,%6,%7}, {%8,%9}, {%0,%1,%2,%3};"               \
        : "+f"((d)[0]), "+f"((d)[1]), "+f"((d)[2]), "+f"((d)[3])              \
        : "r"(a0), "r"(a1), "r"(a2), "r"(a3), "r"(b0), "r"(b1))
#define LDM4(R, addr)                                                         \
    asm volatile("ldmatrix.sync.aligned.m8n8.x4.shared.b16 {%0,%1,%2,%3}, [%4];" \
        : "=r"((R)[0]), "=r"((R)[1]), "=r"((R)[2]), "=r"((R)[3])              \
        : "r"(addr))
#define LDM4T(R, addr)                                                        \
    asm volatile("ldmatrix.sync.aligned.m8n8.x4.trans.shared.b16 {%0,%1,%2,%3}, [%4];" \
        : "=r"((R)[0]), "=r"((R)[1]), "=r"((R)[2]), "=r"((R)[3])              \
        : "r"(addr))

// ---------------- prep+router fused launch ----------------
// blocks [0, ROUTER_BLOCKS): router (top-4 per token, 8 tokens/block)
// blocks [ROUTER_BLOCKS, ...): grid-stride fp32->fp16 convert of weights + x
__global__ void prep_router_kernel(const float* __restrict__ x,
                                   const float* __restrict__ gw,
                                   const float* __restrict__ wg,
                                   const float* __restrict__ wu,
                                   const float* __restrict__ wd) {
    if (blockIdx.x == 0 && threadIdx.x < 34) {
        if (threadIdx.x < 32) g_cnt[threadIdx.x] = 0;
        else if (threadIdx.x == 32) g_done = 0;
        else g_ticket = 0;
    }
    if (blockIdx.x < ROUTER_BLOCKS) {
        // ---- router part ----
        __shared__ float xs[8][HDIM];
        int t0 = blockIdx.x * 8;
        for (int i = threadIdx.x; i < 8 * (HDIM / 4); i += blockDim.x) {
            int row = i >> 8;
            int c4  = i & 255;
            ((float4*)xs[row])[c4] =
                ((const float4*)(x + (size_t)(t0 + row) * HDIM))[c4];
        }
        __syncthreads();

        int w = threadIdx.x >> 5;
        int lane = threadIdx.x & 31;
        int t = t0 + w;
        const float* xr = xs[w];

        float myLogit = 0.f;
        for (int e = 0; e < NEXP; ++e) {
            const float* wr = gw + (size_t)e * HDIM;
            float s = 0.f;
            #pragma unroll 8
            for (int j = lane; j < HDIM; j += 32) s += xr[j] * wr[j];
            #pragma unroll
            for (int off = 16; off; off >>= 1)
                s += __shfl_xor_sync(0xffffffffu, s, off);
            if (lane == e) myLogit = s;
        }

        float v = myLogit;
        float selv[TOPK];
        int   seli[TOPK];
        #pragma unroll
        for (int k = 0; k < TOPK; ++k) {
            float bv = v; int bi = lane;
            #pragma unroll
            for (int off = 16; off; off >>= 1) {
                float ov = __shfl_xor_sync(0xffffffffu, bv, off);
                int   oi = __shfl_xor_sync(0xffffffffu, bi, off);
                if (ov > bv || (ov == bv && oi < bi)) { bv = ov; bi = oi; }
            }
            selv[k] = bv; seli[k] = bi;
            if (lane == bi) v = -1e30f;
        }

        if (lane == 0) {
            float m = selv[0];
            float ew[TOPK];
            float sum = 0.f;
            #pragma unroll
            for (int k = 0; k < TOPK; ++k) { ew[k] = expf(selv[k] - m); sum += ew[k]; }
            float inv = 1.f / sum;
            #pragma unroll
            for (int k = 0; k < TOPK; ++k) {
                g_top_idx[t * TOPK + k] = seli[k];
                g_top_wt [t * TOPK + k] = ew[k] * inv;
            }
        }
        return;
    }
    // ---- convert part ----
    const size_t W4 = (size_t)NEXP * HDIM * IDIM / 4;      // float4 units per weight
    const size_t X4 = (size_t)T_TOKENS * HDIM / 4;
    const size_t total = 3 * W4 + X4;
    size_t nconv = (size_t)(gridDim.x - ROUTER_BLOCKS) * blockDim.x;
    for (size_t i = (size_t)(blockIdx.x - ROUTER_BLOCKS) * blockDim.x + threadIdx.x;
         i < total; i += nconv) {
        const float4* src;
        __half2* dst;
        size_t off;
        if (i < W4)            { src = (const float4*)wg; dst = (__half2*)g_wgh; off = i; }
        else if (i < 2 * W4)   { src = (const float4*)wu; dst = (__half2*)g_wuh; off = i - W4; }
        else if (i < 3 * W4)   { src = (const float4*)wd; dst = (__half2*)g_wdh; off = i - 2 * W4; }
        else                   { src = (const float4*)x;  dst = (__half2*)g_xh;  off = i - 3 * W4; }
        float4 f = src[off];
        dst[2 * off]     = __floats2half2_rn(f.x, f.y);
        dst[2 * off + 1] = __floats2half2_rn(f.z, f.w);
    }
}

// ---------------- scatter + last-block prefix/tile-list ----------------
__global__ void scatter_prefix_kernel() {
    int t = blockIdx.x * blockDim.x + threadIdx.x;
    if (t < T_TOKENS) {
        #pragma unroll
        for (int k = 0; k < TOPK; ++k) {
            int e = g_top_idx[t * TOPK + k];
            int pos = atomicAdd(&g_cnt[e], 1);
            g_etok[e * T_TOKENS + pos] = (t << 2) | k;
            g_ewt [e * T_TOKENS + pos] = g_top_wt[t * TOPK + k];
        }
    }
    __threadfence();
    __syncthreads();
    if (threadIdx.x == 0) {
        int d = atomicAdd(&g_done, 1);
        if (d == (int)gridDim.x - 1) {
            int a = 0, nt = 0;
            for (int e = 0; e < NEXP; ++e) {
                g_off[e] = a;
                int c = *(volatile int*)&g_cnt[e];
                a += c;
                int nt_e = (c + TILE_M - 1) / TILE_M;
                for (int q = 0; q < nt_e; ++q) g_tiles[nt++] = (e << 16) | q;
            }
            g_ntiles = nt;
            g_ticket = 0;
            __threadfence();
        }
    }
}

// ---------------- expert: fp16 mma + trans-ldmatrix B + 3-stage cp.async ----
__global__ void __launch_bounds__(256, 2)
expert_mma() {
    extern __shared__ char sm[];
    __shared__ int   s_tok[TILE_M];
    __shared__ int   s_slot[TILE_M];
    __shared__ float s_wt[TILE_M];
    __shared__ int   s_tile;

    uint32_t smb = smem_u32(sm);
    int tid = threadIdx.x;
    int wid = tid >> 5, lane = tid & 31;
    int gr = lane >> 2, tig = lane & 3;
    int m0 = (wid & 3) * 32;
    int gsel = wid >> 2;
    int n0a = gsel * 32;
    int n0b = gsel * 64;

    // A (row-major [m][k], 144B rows): lanes 0-15 rows, k-halves via bit4
    uint32_t aoff = (uint32_t)(m0 + (lane & 15)) * 144 + ((lane >> 4) & 1) * 16;
    // B (k-major [k][n] rows), trans-ldmatrix: lanes 0-15 k-rows, n-halves via bit4
    uint32_t tk = (uint32_t)(lane & 15);
    uint32_t tn = ((lane >> 4) & 1) * 16;
    uint32_t gboff = (uint32_t)WG_OFF + tk * 144 + (uint32_t)n0a * 2 + tn;
    uint32_t uboff = (uint32_t)WU_OFF + tk * 144 + (uint32_t)n0a * 2 + tn;
    uint32_t dboff = (uint32_t)WD_OFF + tk * 272 + (uint32_t)n0b * 2 + tn;

    for (;;) {
        __syncthreads();
        if (tid == 0) s_tile = atomicAdd(&g_ticket, 1);
        __syncthreads();
        int tI = s_tile;
        if (tI >= g_ntiles) return;
        int pk_t = g_tiles[tI];
        int e = pk_t >> 16;
        int start = (pk_t & 0xffff) * TILE_M;
        int cnt = g_cnt[e];
        int rows = min(TILE_M, cnt - start);

        if (tid < TILE_M) {
            if (tid < rows) {
                int pk = g_etok[e * T_TOKENS + start + tid];
                s_tok[tid] = pk >> 2; s_slot[tid] = pk & 3;
                s_wt[tid] = g_ewt[e * T_TOKENS + start + tid];
            } else { s_tok[tid] = 0; s_slot[tid] = 0; s_wt[tid] = 0.f; }
        }
        __syncthreads();

        const __half* wghE = g_wgh + (size_t)e * HDIM * IDIM;
        const __half* wuhE = g_wuh + (size_t)e * HDIM * IDIM;
        const __half* wdhE = g_wdh + (size_t)e * HDIM * IDIM;
        int hbase = g_off[e] + start;

        // ============== Phase A: h = silu(x Wg) * (x Wu) ==============
        for (int nb = 0; nb < IDIM / 64; ++nb) {
            float accg[2][4][4], accu[2][4][4];
            #pragma unroll
            for (int i = 0; i < 2; ++i)
                #pragma unroll
                for (int j = 0; j < 4; ++j)
                    #pragma unroll
                    for (int q = 0; q < 4; ++q) { accg[i][j][q] = 0.f; accu[i][j][q] = 0.f; }

            // stage: X [128m x 64k] rows 144B; Wg/Wu [64k x 64n] rows 144B
            #define STAGE_A(c)  do {                                               \
                uint32_t sb = smb + ((c) % NSTAGE) * STAGE;                        \
                int k0 = (c) * KC;                                                 \
                _Pragma("unroll")                                                  \
                for (int i2 = 0; i2 < 4; ++i2) {                                   \
                    int idx = tid + i2 * 256;                                      \
                    int m = idx >> 3, seg = idx & 7;                               \
                    cpa16(sb + m * 144 + seg * 16,                                 \
                          g_xh + (size_t)s_tok[m] * HDIM + k0 + seg * 8,           \
                          (m < rows) ? 16 : 0);                                    \
                }                                                                  \
                _Pragma("unroll")                                                  \
                for (int i2 = 0; i2 < 2; ++i2) {                                   \
                    int idx = tid + i2 * 256;                                      \
                    int kk = idx >> 3, seg = idx & 7;                              \
                    cpa16(sb + WG_OFF + kk * 144 + seg * 16,                       \
                          wghE + (size_t)(k0 + kk) * IDIM + nb * 64 + seg * 8, 16);\
                    cpa16(sb + WU_OFF + kk * 144 + seg * 16,                       \
                          wuhE + (size_t)(k0 + kk) * IDIM + nb * 64 + seg * 8, 16);\
                }                                                                  \
                CP_COMMIT();                                                       \
            } while (0)

            STAGE_A(0);
            STAGE_A(1);
            for (int c = 0; c < HDIM / KC; ++c) {
                CP_WAIT(1);
                __syncthreads();
                uint32_t sb = smb + (c % NSTAGE) * STAGE;
                #pragma unroll
                for (int ks = 0; ks < 4; ++ks) {
                    uint32_t a0[4], a1[4], bg0[4], bg1[4], bu0[4], bu1[4];
                    LDM4(a0, sb + aoff + ks * 32);
                    LDM4(a1, sb + aoff + 2304 + ks * 32);
                    LDM4T(bg0, sb + gboff + ks * 2304);
                    LDM4T(bg1, sb + gboff + ks * 2304 + 32);
                    LDM4T(bu0, sb + uboff + ks * 2304);
                    LDM4T(bu1, sb + uboff + ks * 2304 + 32);
                    MMAH(accg[0][0], a0[0], a0[1], a0[2], a0[3], bg0[0], bg0[1]);
                    MMAH(accg[1][0], a1[0], a1[1], a1[2], a1[3], bg0[0], bg0[1]);
                    MMAH(accg[0][1], a0[0], a0[1], a0[2], a0[3], bg0[2], bg0[3]);
                    MMAH(accg[1][1], a1[0], a1[1], a1[2], a1[3], bg0[2], bg0[3]);
                    MMAH(accg[0][2], a0[0], a0[1], a0[2], a0[3], bg1[0], bg1[1]);
                    MMAH(accg[1][2], a1[0], a1[1], a1[2], a1[3], bg1[0], bg1[1]);
                    MMAH(accg[0][3], a0[0], a0[1], a0[2], a0[3], bg1[2], bg1[3]);
                    MMAH(accg[1][3], a1[0], a1[1], a1[2], a1[3], bg1[2], bg1[3]);
                    MMAH(accu[0][0], a0[0], a0[1], a0[2], a0[3], bu0[0], bu0[1]);
                    MMAH(accu[1][0], a1[0], a1[1], a1[2], a1[3], bu0[0], bu0[1]);
                    MMAH(accu[0][1], a0[0], a0[1], a0[2], a0[3], bu0[2], bu0[3]);
                    MMAH(accu[1][1], a1[0], a1[1], a1[2], a1[3], bu0[2], bu0[3]);
                    MMAH(accu[0][2], a0[0], a0[1], a0[2], a0[3], bu1[0], bu1[1]);
                    MMAH(accu[1][2], a1[0], a1[1], a1[2], a1[3], bu1[0], bu1[1]);
                    MMAH(accu[0][3], a0[0], a0[1], a0[2], a0[3], bu1[2], bu1[3]);
                    MMAH(accu[1][3], a1[0], a1[1], a1[2], a1[3], bu1[2], bu1[3]);
                }
                if (c + 2 < HDIM / KC) STAGE_A(c + 2);
                else CP_COMMIT();
            }
            #undef STAGE_A

            // epilogue: silu(gate)*up -> g_hh (fp16)
            #pragma unroll
            for (int i = 0; i < 2; ++i) {
                #pragma unroll
                for (int half = 0; half < 2; ++half) {
                    int m = m0 + 16 * i + gr + 8 * half;
                    if (m < rows) {
                        __half* hp = g_hh + (size_t)(hbase + m) * IDIM + nb * 64 + n0a;
                        #pragma unroll
                        for (int j = 0; j < 4; ++j) {
                            float g0 = accg[i][j][half * 2 + 0];
                            float g1 = accg[i][j][half * 2 + 1];
                            float u0 = accu[i][j][half * 2 + 0];
                            float u1 = accu[i][j][half * 2 + 1];
                            float h0 = u0 * g0 / (1.f + __expf(-g0));
                            float h1 = u1 * g1 / (1.f + __expf(-g1));
                            *(__half2*)(hp + 8 * j + 2 * tig) = __floats2half2_rn(h0, h1);
                        }
                    }
                }
            }
            __syncthreads();
        }

        // ============== Phase B: y = (h Wd) * route_w ==============
        for (int nb = 0; nb < HDIM / 128; ++nb) {
            float acc[2][8][4];
            #pragma unroll
            for (int i = 0; i < 2; ++i)
                #pragma unroll
                for (int j = 0; j < 8; ++j)
                    #pragma unroll
                    for (int q = 0; q < 4; ++q) acc[i][j][q] = 0.f;

            // stage: h [128m x 64k] rows 144B; Wd [64k x 128n] rows 272B
            #define STAGE_B(c)  do {                                               \
                uint32_t sb = smb + ((c) % NSTAGE) * STAGE;                        \
                int k0 = (c) * KC;                                                 \
                _Pragma("unroll")                                                  \
                for (int i2 = 0; i2 < 4; ++i2) {                                   \
                    int idx = tid + i2 * 256;                                      \
                    int m = idx >> 3, seg = idx & 7;                               \
                    cpa16(sb + m * 144 + seg * 16,                                 \
                          g_hh + (size_t)(hbase + m) * IDIM + k0 + seg * 8,        \
                          (m < rows) ? 16 : 0);                                    \
                }                                                                  \
                _Pragma("unroll")                                                  \
                for (int i2 = 0; i2 < 4; ++i2) {                                   \
                    int idx = tid + i2 * 256;                                      \
                    int kk = idx >> 4, seg = idx & 15;                             \
                    cpa16(sb + WD_OFF + kk * 272 + seg * 16,                       \
                          wdhE + (size_t)(k0 + kk) * HDIM + nb * 128 + seg * 8, 16);\
                }                                                                  \
                CP_COMMIT();                                                       \
            } while (0)

            STAGE_B(0);
            STAGE_B(1);
            for (int c = 0; c < IDIM / KC; ++c) {
                CP_WAIT(1);
                __syncthreads();
                uint32_t sb = smb + (c % NSTAGE) * STAGE;
                #pragma unroll
                for (int ks = 0; ks < 4; ++ks) {
                    uint32_t a0[4], a1[4], b0[4], b1[4], b2[4], b3[4];
                    LDM4(a0, sb + aoff + ks * 32);
                    LDM4(a1, sb + aoff + 2304 + ks * 32);
                    LDM4T(b0, sb + dboff + ks * 4352);
                    LDM4T(b1, sb + dboff + ks * 4352 + 32);
                    LDM4T(b2, sb + dboff + ks * 4352 + 64);
                    LDM4T(b3, sb + dboff + ks * 4352 + 96);
                    MMAH(acc[0][0], a0[0], a0[1], a0[2], a0[3], b0[0], b0[1]);
                    MMAH(acc[1][0], a1[0], a1[1], a1[2], a1[3], b0[0], b0[1]);
                    MMAH(acc[0][1], a0[0], a0[1], a0[2], a0[3], b0[2], b0[3]);
                    MMAH(acc[1][1], a1[0], a1[1], a1[2], a1[3], b0[2], b0[3]);
                    MMAH(acc[0][2], a0[0], a0[1], a0[2], a0[3], b1[0], b1[1]);
                    MMAH(acc[1][2], a1[0], a1[1], a1[2], a1[3], b1[0], b1[1]);
                    MMAH(acc[0][3], a0[0], a0[1], a0[2], a0[3], b1[2], b1[3]);
                    MMAH(acc[1][3], a1[0], a1[1], a1[2], a1[3], b1[2], b1[3]);
                    MMAH(acc[0][4], a0[0], a0[1], a0[2], a0[3], b2[0], b2[1]);
                    MMAH(acc[1][4], a1[0], a1[1], a1[2], a1[3], b2[0], b2[1]);
                    MMAH(acc[0][5], a0[0], a0[1], a0[2], a0[3], b2[2], b2[3]);
                    MMAH(acc[1][5], a1[0], a1[1], a1[2], a1[3], b2[2], b2[3]);
                    MMAH(acc[0][6], a0[0], a0[1], a0[2], a0[3], b3[0], b3[1]);
                    MMAH(acc[1][6], a1[0], a1[1], a1[2], a1[3], b3[0], b3[1]);
                    MMAH(acc[0][7], a0[0], a0[1], a0[2], a0[3], b3[2], b3[3]);
                    MMAH(acc[1][7], a1[0], a1[1], a1[2], a1[3], b3[2], b3[3]);
                }
                if (c + 2 < IDIM / KC) STAGE_B(c + 2);
                else CP_COMMIT();
            }
            #undef STAGE_B

            // epilogue: apply routing weight (fp32), store fp16 partials
            #pragma unroll
            for (int i = 0; i < 2; ++i) {
                #pragma unroll
                for (int half = 0; half < 2; ++half) {
                    int m = m0 + 16 * i + gr + 8 * half;
                    if (m < rows) {
                        float wgt = s_wt[m];
                        __half* dp = g_partial +
                            ((size_t)s_tok[m] * TOPK + s_slot[m]) * HDIM + nb * 128 + n0b;
                        #pragma unroll
                        for (int j = 0; j < 8; ++j) {
                            float y0 = wgt * acc[i][j][half * 2 + 0];
                            float y1 = wgt * acc[i][j][half * 2 + 1];
                            *(__half2*)(dp + 8 * j + 2 * tig) = __floats2half2_rn(y0, y1);
                        }
                    }
                }
            }
            __syncthreads();
        }
    }
}

// ---------------- combine: out[t][h] = sum_k partial[t][k][h] (fp16 in) -----
__global__ void combine_kernel(float* __restrict__ out) {
    size_t i = (size_t)blockIdx.x * blockDim.x + threadIdx.x;  // float4 index
    size_t t = i >> 8;                 // 256 float4 per token row
    size_t c = i & 255;
    const __half2* s = (const __half2*)g_partial;
    // half2 layout: token stride = 2048, slot stride = 512, col pair index = c*2
    size_t base = t * (TOPK * 512) + c * 2;
    float4 o = make_float4(0.f, 0.f, 0.f, 0.f);
    #pragma unroll
    for (int slot = 0; slot < TOPK; ++slot) {
        __half2 p0 = s[base + slot * 512];
        __half2 p1 = s[base + slot * 512 + 1];
        float2 f0 = __half22float2(p0);
        float2 f1 = __half22float2(p1);
        o.x += f0.x; o.y += f0.y; o.z += f1.x; o.w += f1.y;
    }
    ((float4*)out)[i] = o;
}

// ---------------- launch ---------------------------------------------------
extern "C" void kernel_launch(void* const* d_in, const int* in_sizes, int n_in,
                              void* d_out, int out_size) {
    const float* x  = (const float*)d_in[0];
    const float* gw = (const float*)d_in[1];
    const float* wg = (const float*)d_in[2];
    const float* wu = (const float*)d_in[3];
    const float* wd = (const float*)d_in[4];
    float* out = (float*)d_out;

    prep_router_kernel<<<ROUTER_BLOCKS + 4736, 256>>>(x, gw, wg, wu, wd);
    scatter_prefix_kernel<<<T_TOKENS / 256, 256>>>();

    int smem = NSTAGE * STAGE;
    cudaFuncSetAttribute(expert_mma,
                         cudaFuncAttributeMaxDynamicSharedMemorySize, smem);
    expert_mma<<<296, 256, smem>>>();

    combine_kernel<<<(T_TOKENS * HDIM / 4) / 256, 256>>>(out);
}